// round 3
// baseline (speedup 1.0000x reference)
#include <cuda_runtime.h>
#include <math.h>

// ---------------- problem constants ----------------
#define BB   2
#define CC   320
#define NNODE 1024
#define NH   8
#define DH   40
#define LLAYERS 2
#define C2   640
#define C3   960
#define AA   16
#define EPD  64

#define EDGE_SCALE 0.17677669529663687f  // 32^-0.5
#define ATTN_SCALE 0.15811388300841897f  // 40^-0.5
#define LN_EPS 1e-5f

// ---------------- scratch ----------------
static __device__ float g_node[BB * NNODE * CC];
static __device__ float g_qk[BB * NNODE * C2];
static __device__ float g_y[BB * NNODE * CC];
static __device__ float g_qkv[BB * NNODE * C3];
static __device__ float g_edge[BB * NNODE * NNODE];
static __device__ float g_nodeout[BB * NNODE * CC];
static __device__ float g_s[BB * CC];

// ---------------- tf32 helpers ----------------
__device__ __forceinline__ unsigned f2tf(float f) {
    unsigned r;
    asm("cvt.rna.tf32.f32 %0, %1;" : "=r"(r) : "f"(f));
    return r;
}
__device__ __forceinline__ float f2tf_f(float f) {
    return __uint_as_float(f2tf(f));
}
__device__ __forceinline__ void mma_tf32(float (&c)[4], unsigned a0, unsigned a1,
                                         unsigned a2, unsigned a3, unsigned b0,
                                         unsigned b1) {
    asm volatile(
        "mma.sync.aligned.m16n8k8.row.col.f32.tf32.tf32.f32 "
        "{%0,%1,%2,%3},{%4,%5,%6,%7},{%8,%9},{%0,%1,%2,%3};"
        : "+f"(c[0]), "+f"(c[1]), "+f"(c[2]), "+f"(c[3])
        : "r"(a0), "r"(a1), "r"(a2), "r"(a3), "r"(b0), "r"(b1));
}

// ---------------- reductions ----------------
__device__ __forceinline__ float warpRedSum(float v) {
#pragma unroll
    for (int o = 16; o; o >>= 1) v += __shfl_xor_sync(0xffffffffu, v, o);
    return v;
}
__device__ __forceinline__ float warpRedMax(float v) {
#pragma unroll
    for (int o = 16; o; o >>= 1) v = fmaxf(v, __shfl_xor_sync(0xffffffffu, v, o));
    return v;
}
__device__ __forceinline__ float blockSum(float v, float* sh) {
    v = warpRedSum(v);
    if ((threadIdx.x & 31) == 0) sh[threadIdx.x >> 5] = v;
    __syncthreads();
    float r = sh[0];
#pragma unroll
    for (int i = 1; i < 8; i++) r += sh[i];
    __syncthreads();
    return r;
}
__device__ __forceinline__ float blockMax(float v, float* sh) {
    v = warpRedMax(v);
    if ((threadIdx.x & 31) == 0) sh[threadIdx.x >> 5] = v;
    __syncthreads();
    float r = sh[0];
#pragma unroll
    for (int i = 1; i < 8; i++) r = fmaxf(r, sh[i]);
    __syncthreads();
    return r;
}

// ---------------- transposes ----------------
__global__ void k_tin(const float* __restrict__ x, float* __restrict__ node) {
    __shared__ float t[32][33];
    int b = blockIdx.z;
    int c0 = blockIdx.y * 32, n0 = blockIdx.x * 32;
#pragma unroll
    for (int i = 0; i < 4; i++)
        t[threadIdx.y + i * 8][threadIdx.x] =
            x[((size_t)b * CC + c0 + threadIdx.y + i * 8) * NNODE + n0 + threadIdx.x];
    __syncthreads();
#pragma unroll
    for (int i = 0; i < 4; i++)
        node[((size_t)b * NNODE + n0 + threadIdx.y + i * 8) * CC + c0 + threadIdx.x] =
            t[threadIdx.x][threadIdx.y + i * 8];
}

__global__ void k_tout(const float* __restrict__ node, float* __restrict__ out) {
    __shared__ float t[32][33];
    int b = blockIdx.z;
    int c0 = blockIdx.y * 32, n0 = blockIdx.x * 32;
#pragma unroll
    for (int i = 0; i < 4; i++)
        t[threadIdx.y + i * 8][threadIdx.x] =
            node[((size_t)b * NNODE + n0 + threadIdx.y + i * 8) * CC + c0 + threadIdx.x];
    __syncthreads();
#pragma unroll
    for (int i = 0; i < 4; i++)
        out[((size_t)b * CC + c0 + threadIdx.y + i * 8) * NNODE + n0 + threadIdx.x] =
            t[threadIdx.x][threadIdx.y + i * 8];
}

// ---------------- prior sum ----------------
__global__ void k_prior(const float* __restrict__ da, const float* __restrict__ w,
                        const float* __restrict__ bfc, float* __restrict__ s) {
    int t = blockIdx.x * blockDim.x + threadIdx.x;
    if (t >= BB * CC) return;
    int b = t / CC, c = t % CC;
    float acc = (float)AA * bfc[c];
    for (int e = 0; e < EPD; e++) {
        float sa = 0.f;
#pragma unroll
        for (int a = 0; a < AA; a++) sa += da[((size_t)b * AA + a) * EPD + e];
        acc += sa * w[c * EPD + e];
    }
    s[t] = acc;
}

// ============ generic tf32 NT GEMM (unchanged from R2) ============
__global__ void k_mm(const float* __restrict__ A, int lda, size_t sA,
                     const float* __restrict__ W, int ldw, size_t sW,
                     float* __restrict__ Cc, int ldc, size_t sC, int K, float alpha,
                     const float* __restrict__ bias) {
    int bz = blockIdx.z;
    A += (size_t)bz * sA;
    W += (size_t)bz * sW;
    Cc += (size_t)bz * sC;
    __shared__ float As[16][136];
    __shared__ float Ws[16][72];
    int m0 = blockIdx.y * 128, n0 = blockIdx.x * 64;
    int tid = threadIdx.x;
    int warp = tid >> 5, lane = tid & 31;
    int wm = (warp >> 1) * 32, wn = (warp & 1) * 32;
    int lq = lane >> 2, lr = lane & 3;
    float acc[2][4][4] = {};
    for (int k0 = 0; k0 < K; k0 += 16) {
#pragma unroll
        for (int i = 0; i < 8; i++) {
            int idx = tid + i * 256;
            int kk = idx & 15, r = idx >> 4;
            As[kk][r] = f2tf_f(A[(size_t)(m0 + r) * lda + k0 + kk]);
        }
#pragma unroll
        for (int i = 0; i < 4; i++) {
            int idx = tid + i * 256;
            int kk = idx & 15, r = idx >> 4;
            Ws[kk][r] = f2tf_f(W[(size_t)(n0 + r) * ldw + k0 + kk]);
        }
        __syncthreads();
#pragma unroll
        for (int kh = 0; kh < 2; kh++) {
            int kb = kh * 8;
            unsigned a[2][4], b[4][2];
#pragma unroll
            for (int mt = 0; mt < 2; mt++) {
                int mb = wm + mt * 16;
                a[mt][0] = __float_as_uint(As[kb + lr][mb + lq]);
                a[mt][1] = __float_as_uint(As[kb + lr][mb + lq + 8]);
                a[mt][2] = __float_as_uint(As[kb + 4 + lr][mb + lq]);
                a[mt][3] = __float_as_uint(As[kb + 4 + lr][mb + lq + 8]);
            }
#pragma unroll
            for (int nt = 0; nt < 4; nt++) {
                int nb = wn + nt * 8;
                b[nt][0] = __float_as_uint(Ws[kb + lr][nb + lq]);
                b[nt][1] = __float_as_uint(Ws[kb + 4 + lr][nb + lq]);
            }
#pragma unroll
            for (int mt = 0; mt < 2; mt++)
#pragma unroll
                for (int nt = 0; nt < 4; nt++)
                    mma_tf32(acc[mt][nt], a[mt][0], a[mt][1], a[mt][2], a[mt][3],
                             b[nt][0], b[nt][1]);
        }
        __syncthreads();
    }
#pragma unroll
    for (int mt = 0; mt < 2; mt++) {
#pragma unroll
        for (int nt = 0; nt < 4; nt++) {
            int gc = n0 + wn + nt * 8 + 2 * lr;
            float bi0 = bias ? bias[gc] : 0.f;
            float bi1 = bias ? bias[gc + 1] : 0.f;
#pragma unroll
            for (int half = 0; half < 2; half++) {
                int gr = m0 + wm + mt * 16 + lq + half * 8;
                float2 v;
                v.x = alpha * acc[mt][nt][half * 2] + bi0;
                v.y = alpha * acc[mt][nt][half * 2 + 1] + bi1;
                *reinterpret_cast<float2*>(&Cc[(size_t)gr * ldc + gc]) = v;
            }
        }
    }
}

// ---------------- row softmax in-place on [B*N, N] ----------------
__global__ void k_row_softmax(float* __restrict__ E) {
    size_t off = (size_t)blockIdx.x * NNODE;
    __shared__ float row[NNODE];
    __shared__ float sh[8];
    int tid = threadIdx.x;
    float lmax = -3.4e38f;
    for (int i = tid; i < NNODE; i += 256) {
        float v = E[off + i];
        row[i] = v;
        lmax = fmaxf(lmax, v);
    }
    float mx = blockMax(lmax, sh);
    float ls = 0.f;
    for (int i = tid; i < NNODE; i += 256) {
        float e = __expf(row[i] - mx);
        row[i] = e;
        ls += e;
    }
    float Z = blockSum(ls, sh);
    float invZ = 1.f / Z;
    for (int i = tid; i < NNODE; i += 256) E[off + i] = row[i] * invZ;
}

// ---------------- fused LN1 + graph-mix + LN2 ----------------
__global__ void k_ln_fuse(const float* __restrict__ node, const float* __restrict__ edge,
                          const float* __restrict__ s,
                          const float* __restrict__ g1, const float* __restrict__ b1,
                          const float* __restrict__ g2, const float* __restrict__ b2,
                          float* __restrict__ y) {
    int bn = blockIdx.x;
    int b = bn >> 10, n = bn & 1023;
    __shared__ float row[CC];
    __shared__ float sh[8];
    int tid = threadIdx.x;
    const float* xr = node + (size_t)bn * CC;
    float lsum = 0.f, lsq = 0.f;
    for (int c = tid; c < CC; c += 256) {
        float v = xr[c];
        row[c] = v;
        lsum += v;
        lsq += v * v;
    }
    float sum = blockSum(lsum, sh);
    float sq = blockSum(lsq, sh);
    float mean = sum * (1.f / CC);
    float var = sq * (1.f / CC) - mean * mean;
    float inv = rsqrtf(var + LN_EPS);
    float diag = edge[((size_t)b * NNODE + n) * NNODE + n];
    lsum = 0.f;
    lsq = 0.f;
    for (int c = tid; c < CC; c += 256) {
        float nt = (row[c] - mean) * inv * g1[c] + b1[c];
        float n2 = diag * nt * s[b * CC + c] + nt;
        row[c] = n2;
        lsum += n2;
        lsq += n2 * n2;
    }
    float sum2 = blockSum(lsum, sh);
    float sq2 = blockSum(lsq, sh);
    float mean2 = sum2 * (1.f / CC);
    float var2 = sq2 * (1.f / CC) - mean2 * mean2;
    float inv2 = rsqrtf(var2 + LN_EPS);
    float* yr = y + (size_t)bn * CC;
    for (int c = tid; c < CC; c += 256)
        yr[c] = (row[c] - mean2) * inv2 * g2[c] + b2[c];
}

// ================= fused attention: logits+softmax+ednew+AV+edge update =========
// grid (N/16, B), 256 threads. Dynamic smem layout (floats):
//  S  [16][1028]  logits -> probs                 @ 0       (16448)
//  EN [16][1024]  sum_h rw*(p+l)                  @ 16448   (16384)
//  Qh [40][24]    tf32 Q head tile                @ 32832   (960)
//  Ks [40][72]    tf32 K chunk (64 nodes)         @ 33792   (2880)
//  Vs [128][40]   tf32 V chunk (128 nodes)        @ 36672   (5120)
#define FA_SMEM_FLOATS 41792
__global__ void __launch_bounds__(256, 1)
k_fattn(const float* __restrict__ qkv, float* __restrict__ edge,
        float* __restrict__ nodeout,
        const float* __restrict__ exp_w, const float* __restrict__ exp_b,
        const float* __restrict__ red_w, const float* __restrict__ red_b) {
    extern __shared__ float sm[];
    float* S = sm;
    float* EN = sm + 16448;
    float* Qh = sm + 32832;
    float* Ks = sm + 33792;
    float* Vs = sm + 36672;
    int n0 = blockIdx.x * 16;
    int b = blockIdx.y;
    int tid = threadIdx.x, warp = tid >> 5, lane = tid & 31;
    int lq = lane >> 2, lr = lane & 3;
    const float* qbase = qkv + (size_t)b * NNODE * C3;
    float* erow = edge + ((size_t)b * NNODE + n0) * NNODE;
    float* nbase = nodeout + ((size_t)b * NNODE + n0) * CC;

    for (int i = tid; i < 16 * 1024; i += 256) EN[i] = 0.f;

    for (int h = 0; h < NH; h++) {
        __syncthreads();  // protect S/Qh from previous head usage
        // Q head tile -> Qh[d][r]
        for (int i = tid; i < 16 * DH; i += 256) {
            int r = i / DH, d = i - r * DH;
            Qh[d * 24 + r] = f2tf_f(qbase[(size_t)(n0 + r) * C3 + h * DH + d]);
        }
        float ew = exp_w[h], eb = exp_b[h];
        const float* kbase = qbase + CC + h * DH;
        // ---- logits: m-chunks of 64 ----
        for (int m0 = 0; m0 < NNODE; m0 += 64) {
            __syncthreads();
            for (int i = tid; i < 64 * DH; i += 256) {
                int j = i / DH, d = i - j * DH;
                Ks[d * 72 + j] = f2tf_f(kbase[(size_t)(m0 + j) * C3 + d]);
            }
            __syncthreads();
            float acc[4] = {};
            int nb = warp * 8;
#pragma unroll
            for (int ks = 0; ks < 5; ks++) {
                int kb = ks * 8;
                unsigned a0 = __float_as_uint(Qh[(kb + lr) * 24 + lq]);
                unsigned a1 = __float_as_uint(Qh[(kb + lr) * 24 + lq + 8]);
                unsigned a2 = __float_as_uint(Qh[(kb + 4 + lr) * 24 + lq]);
                unsigned a3 = __float_as_uint(Qh[(kb + 4 + lr) * 24 + lq + 8]);
                unsigned b0 = __float_as_uint(Ks[(kb + lr) * 72 + nb + lq]);
                unsigned b1 = __float_as_uint(Ks[(kb + 4 + lr) * 72 + nb + lq]);
                mma_tf32(acc, a0, a1, a2, a3, b0, b1);
            }
            int gc = m0 + nb + 2 * lr;
            float2 e0 = *reinterpret_cast<const float2*>(&erow[(size_t)lq * NNODE + gc]);
            float2 e1 =
                *reinterpret_cast<const float2*>(&erow[(size_t)(lq + 8) * NNODE + gc]);
            float2 v0, v1;
            v0.x = acc[0] * ATTN_SCALE + ew * e0.x + eb;
            v0.y = acc[1] * ATTN_SCALE + ew * e0.y + eb;
            v1.x = acc[2] * ATTN_SCALE + ew * e1.x + eb;
            v1.y = acc[3] * ATTN_SCALE + ew * e1.y + eb;
            *reinterpret_cast<float2*>(&S[lq * 1028 + gc]) = v0;
            *reinterpret_cast<float2*>(&S[(lq + 8) * 1028 + gc]) = v1;
        }
        __syncthreads();
        // ---- softmax + EN accumulate: warp per 2 rows ----
        float rw = red_w[h];
#pragma unroll
        for (int rr = 0; rr < 2; rr++) {
            int r = warp * 2 + rr;
            float mx = -3.4e38f;
            for (int m = lane; m < NNODE; m += 32) mx = fmaxf(mx, S[r * 1028 + m]);
            mx = warpRedMax(mx);
            float sum = 0.f;
            for (int m = lane; m < NNODE; m += 32) {
                float l = S[r * 1028 + m];
                float e = __expf(l - mx);
                sum += e;
                S[r * 1028 + m] = e;
                EN[r * 1024 + m] += rw * l;
            }
            sum = warpRedSum(sum);
            float invZ = 1.f / sum;
            for (int m = lane; m < NNODE; m += 32) {
                float p = S[r * 1028 + m] * invZ;
                S[r * 1028 + m] = p;
                EN[r * 1024 + m] += rw * p;
            }
        }
        __syncthreads();
        // ---- AV: warps 0..4 each own one n-tile of 8 (DH=40) ----
        float av[4] = {0.f, 0.f, 0.f, 0.f};
        const float* vbase = qbase + 2 * CC + h * DH;
        for (int mv0 = 0; mv0 < NNODE; mv0 += 128) {
            __syncthreads();
            for (int i = tid; i < 128 * DH; i += 256) {
                int j = i / DH, d = i - j * DH;
                Vs[j * 40 + d] = f2tf_f(vbase[(size_t)(mv0 + j) * C3 + d]);
            }
            __syncthreads();
            if (warp < 5) {
#pragma unroll
                for (int ks = 0; ks < 16; ks++) {
                    int kb = ks * 8;
                    unsigned a0 = __float_as_uint(S[lq * 1028 + mv0 + kb + lr]);
                    unsigned a1 = __float_as_uint(S[(lq + 8) * 1028 + mv0 + kb + lr]);
                    unsigned a2 = __float_as_uint(S[lq * 1028 + mv0 + kb + 4 + lr]);
                    unsigned a3 =
                        __float_as_uint(S[(lq + 8) * 1028 + mv0 + kb + 4 + lr]);
                    unsigned b0 = __float_as_uint(Vs[(kb + lr) * 40 + warp * 8 + lq]);
                    unsigned b1 =
                        __float_as_uint(Vs[(kb + 4 + lr) * 40 + warp * 8 + lq]);
                    mma_tf32(av, a0, a1, a2, a3, b0, b1);
                }
            }
        }
        if (warp < 5) {
            int gc = h * DH + warp * 8 + 2 * lr;
            *reinterpret_cast<float2*>(&nbase[(size_t)lq * CC + gc]) =
                make_float2(av[0], av[1]);
            *reinterpret_cast<float2*>(&nbase[(size_t)(lq + 8) * CC + gc]) =
                make_float2(av[2], av[3]);
        }
    }
    __syncthreads();
    // ---- epilogue: per row — wsum, edge += ednew, node_out += wsum ----
    float rb = red_b[0];
#pragma unroll
    for (int rr = 0; rr < 2; rr++) {
        int r = warp * 2 + rr;
        float mx = -3.4e38f;
        for (int m = lane; m < NNODE; m += 32)
            mx = fmaxf(mx, EN[r * 1024 + m] + rb);
        mx = warpRedMax(mx);
        float s1 = 0.f, s2 = 0.f;
        for (int m = lane; m < NNODE; m += 32) {
            float v = EN[r * 1024 + m] + rb;
            float e = __expf(v - mx);
            s1 += e;
            s2 += e * v;
        }
        s1 = warpRedSum(s1);
        s2 = warpRedSum(s2);
        float wsum = s2 / s1;
        for (int m = lane; m < NNODE; m += 32)
            erow[(size_t)r * NNODE + m] += EN[r * 1024 + m] + rb;
        float* np = nbase + (size_t)r * CC;
        for (int c = lane; c < CC; c += 32) np[c] += wsum;
    }
}

// ---------------- launch ----------------
extern "C" void kernel_launch(void* const* d_in, const int* in_sizes, int n_in,
                              void* d_out, int out_size) {
    const float* x = (const float*)d_in[0];
    const float* da_prior = (const float*)d_in[1];
    const float* qk_w = (const float*)d_in[2];
    const float* fcp_w = (const float*)d_in[3];
    const float* fcp_b = (const float*)d_in[4];
    const float* ln1_g = (const float*)d_in[5];
    const float* ln1_b = (const float*)d_in[6];
    const float* gln_g = (const float*)d_in[7];
    const float* gln_b = (const float*)d_in[8];
    const float* qkv_w = (const float*)d_in[9];
    const float* qkv_b = (const float*)d_in[10];
    const float* proj_w = (const float*)d_in[11];
    const float* proj_b = (const float*)d_in[12];
    const float* exp_w = (const float*)d_in[13];
    const float* exp_b = (const float*)d_in[14];
    const float* red_w = (const float*)d_in[15];
    const float* red_b = (const float*)d_in[16];
    float* out = (float*)d_out;

    float *p_node, *p_qk, *p_y, *p_qkv, *p_edge, *p_nodeout, *p_s;
    cudaGetSymbolAddress((void**)&p_node, g_node);
    cudaGetSymbolAddress((void**)&p_qk, g_qk);
    cudaGetSymbolAddress((void**)&p_y, g_y);
    cudaGetSymbolAddress((void**)&p_qkv, g_qkv);
    cudaGetSymbolAddress((void**)&p_edge, g_edge);
    cudaGetSymbolAddress((void**)&p_nodeout, g_nodeout);
    cudaGetSymbolAddress((void**)&p_s, g_s);

    static const size_t fa_smem = FA_SMEM_FLOATS * sizeof(float);
    cudaFuncSetAttribute(k_fattn, cudaFuncAttributeMaxDynamicSharedMemorySize,
                         (int)fa_smem);

    k_tin<<<dim3(NNODE / 32, CC / 32, BB), dim3(32, 8)>>>(x, p_node);
    k_prior<<<3, 256>>>(da_prior, fcp_b ? fcp_w : fcp_w, fcp_b, p_s);
    k_mm<<<dim3(C2 / 64, (BB * NNODE) / 128, 1), 256>>>(
        p_node, CC, 0, qk_w, CC, 0, p_qk, C2, 0, CC, 1.f, nullptr);
    k_mm<<<dim3(NNODE / 64, NNODE / 128, BB), 256>>>(
        p_qk, C2, (size_t)NNODE * C2, p_qk + CC, C2, (size_t)NNODE * C2,
        p_edge, NNODE, (size_t)NNODE * NNODE, CC, EDGE_SCALE, nullptr);
    k_row_softmax<<<BB * NNODE, 256>>>(p_edge);

    for (int l = 0; l < LLAYERS; l++) {
        k_ln_fuse<<<BB * NNODE, 256>>>(p_node, p_edge, p_s,
                                       ln1_g + l * CC, ln1_b + l * CC,
                                       gln_g + l * CC, gln_b + l * CC, p_y);
        k_mm<<<dim3(C3 / 64, (BB * NNODE) / 128, 1), 256>>>(
            p_y, CC, 0, qkv_w + (size_t)l * C3 * CC, CC, 0,
            p_qkv, C3, 0, CC, 1.f, qkv_b + l * C3);
        k_fattn<<<dim3(NNODE / 16, BB), 256, fa_smem>>>(
            p_qkv, p_edge, p_nodeout, exp_w + l * NH, exp_b + l * NH,
            red_w + l * NH, red_b + l);
        k_mm<<<dim3(CC / 64, (BB * NNODE) / 128, 1), 256>>>(
            p_nodeout, CC, 0, proj_w + (size_t)l * CC * CC, CC, 0,
            p_node, CC, 0, CC, 1.f, proj_b + l * CC);
    }

    k_tout<<<dim3(NNODE / 32, CC / 32, BB), dim3(32, 8)>>>(p_node, out);
}

// round 8
// speedup vs baseline: 1.4086x; 1.4086x over previous
#include <cuda_runtime.h>
#include <math.h>

// ---------------- problem constants ----------------
#define BB   2
#define CC   320
#define NNODE 1024
#define NH   8
#define DH   40
#define LLAYERS 2
#define C2   640
#define C3   960
#define AA   16
#define EPD  64

#define EDGE_SCALE 0.17677669529663687f  // 32^-0.5
#define ATTN_SCALE 0.15811388300841897f  // 40^-0.5
#define LN_EPS 1e-5f

// ---------------- scratch ----------------
static __device__ float g_node[BB * NNODE * CC];
static __device__ float g_qk[BB * NNODE * C2];
static __device__ float g_y[BB * NNODE * CC];
static __device__ float g_qkv[BB * NNODE * C3];
static __device__ float g_edge[BB * NNODE * NNODE];
static __device__ float g_hbuf[(size_t)BB * NH * NNODE * NNODE];  // per-head ednew contrib
static __device__ float g_nodeout[BB * NNODE * CC];
static __device__ float g_s[BB * CC];

// ---------------- tf32 helpers ----------------
__device__ __forceinline__ unsigned f2tf(float f) {
    unsigned r;
    asm("cvt.rna.tf32.f32 %0, %1;" : "=r"(r) : "f"(f));
    return r;
}
__device__ __forceinline__ float f2tf_f(float f) {
    return __uint_as_float(f2tf(f));
}
__device__ __forceinline__ void mma_tf32(float (&c)[4], unsigned a0, unsigned a1,
                                         unsigned a2, unsigned a3, unsigned b0,
                                         unsigned b1) {
    asm volatile(
        "mma.sync.aligned.m16n8k8.row.col.f32.tf32.tf32.f32 "
        "{%0,%1,%2,%3},{%4,%5,%6,%7},{%8,%9},{%0,%1,%2,%3};"
        : "+f"(c[0]), "+f"(c[1]), "+f"(c[2]), "+f"(c[3])
        : "r"(a0), "r"(a1), "r"(a2), "r"(a3), "r"(b0), "r"(b1));
}

// ---------------- reductions ----------------
__device__ __forceinline__ float warpRedSum(float v) {
#pragma unroll
    for (int o = 16; o; o >>= 1) v += __shfl_xor_sync(0xffffffffu, v, o);
    return v;
}
__device__ __forceinline__ float warpRedMax(float v) {
#pragma unroll
    for (int o = 16; o; o >>= 1) v = fmaxf(v, __shfl_xor_sync(0xffffffffu, v, o));
    return v;
}
__device__ __forceinline__ float blockSum(float v, float* sh) {
    v = warpRedSum(v);
    if ((threadIdx.x & 31) == 0) sh[threadIdx.x >> 5] = v;
    __syncthreads();
    float r = sh[0];
#pragma unroll
    for (int i = 1; i < 8; i++) r += sh[i];
    __syncthreads();
    return r;
}
__device__ __forceinline__ float blockMax(float v, float* sh) {
    v = warpRedMax(v);
    if ((threadIdx.x & 31) == 0) sh[threadIdx.x >> 5] = v;
    __syncthreads();
    float r = sh[0];
#pragma unroll
    for (int i = 1; i < 8; i++) r = fmaxf(r, sh[i]);
    __syncthreads();
    return r;
}

// ---------------- transposes ----------------
__global__ void k_tin(const float* __restrict__ x, float* __restrict__ node) {
    __shared__ float t[32][33];
    int b = blockIdx.z;
    int c0 = blockIdx.y * 32, n0 = blockIdx.x * 32;
#pragma unroll
    for (int i = 0; i < 4; i++)
        t[threadIdx.y + i * 8][threadIdx.x] =
            x[((size_t)b * CC + c0 + threadIdx.y + i * 8) * NNODE + n0 + threadIdx.x];
    __syncthreads();
#pragma unroll
    for (int i = 0; i < 4; i++)
        node[((size_t)b * NNODE + n0 + threadIdx.y + i * 8) * CC + c0 + threadIdx.x] =
            t[threadIdx.x][threadIdx.y + i * 8];
}

__global__ void k_tout(const float* __restrict__ node, float* __restrict__ out) {
    __shared__ float t[32][33];
    int b = blockIdx.z;
    int c0 = blockIdx.y * 32, n0 = blockIdx.x * 32;
#pragma unroll
    for (int i = 0; i < 4; i++)
        t[threadIdx.y + i * 8][threadIdx.x] =
            node[((size_t)b * NNODE + n0 + threadIdx.y + i * 8) * CC + c0 + threadIdx.x];
    __syncthreads();
#pragma unroll
    for (int i = 0; i < 4; i++)
        out[((size_t)b * CC + c0 + threadIdx.y + i * 8) * NNODE + n0 + threadIdx.x] =
            t[threadIdx.x][threadIdx.y + i * 8];
}

// ---------------- prior sum ----------------
__global__ void k_prior(const float* __restrict__ da, const float* __restrict__ w,
                        const float* __restrict__ bfc, float* __restrict__ s) {
    int t = blockIdx.x * blockDim.x + threadIdx.x;
    if (t >= BB * CC) return;
    int b = t / CC, c = t % CC;
    float acc = (float)AA * bfc[c];
    for (int e = 0; e < EPD; e++) {
        float sa = 0.f;
#pragma unroll
        for (int a = 0; a < AA; a++) sa += da[((size_t)b * AA + a) * EPD + e];
        acc += sa * w[c * EPD + e];
    }
    s[t] = acc;
}

// ============ generic tf32 NT GEMM (proven R2) ============
__global__ void k_mm(const float* __restrict__ A, int lda, size_t sA,
                     const float* __restrict__ W, int ldw, size_t sW,
                     float* __restrict__ Cc, int ldc, size_t sC, int K, float alpha,
                     const float* __restrict__ bias) {
    int bz = blockIdx.z;
    A += (size_t)bz * sA;
    W += (size_t)bz * sW;
    Cc += (size_t)bz * sC;
    __shared__ float As[16][136];
    __shared__ float Ws[16][72];
    int m0 = blockIdx.y * 128, n0 = blockIdx.x * 64;
    int tid = threadIdx.x;
    int warp = tid >> 5, lane = tid & 31;
    int wm = (warp >> 1) * 32, wn = (warp & 1) * 32;
    int lq = lane >> 2, lr = lane & 3;
    float acc[2][4][4] = {};
    for (int k0 = 0; k0 < K; k0 += 16) {
#pragma unroll
        for (int i = 0; i < 8; i++) {
            int idx = tid + i * 256;
            int kk = idx & 15, r = idx >> 4;
            As[kk][r] = f2tf_f(A[(size_t)(m0 + r) * lda + k0 + kk]);
        }
#pragma unroll
        for (int i = 0; i < 4; i++) {
            int idx = tid + i * 256;
            int kk = idx & 15, r = idx >> 4;
            Ws[kk][r] = f2tf_f(W[(size_t)(n0 + r) * ldw + k0 + kk]);
        }
        __syncthreads();
#pragma unroll
        for (int kh = 0; kh < 2; kh++) {
            int kb = kh * 8;
            unsigned a[2][4], b[4][2];
#pragma unroll
            for (int mt = 0; mt < 2; mt++) {
                int mb = wm + mt * 16;
                a[mt][0] = __float_as_uint(As[kb + lr][mb + lq]);
                a[mt][1] = __float_as_uint(As[kb + lr][mb + lq + 8]);
                a[mt][2] = __float_as_uint(As[kb + 4 + lr][mb + lq]);
                a[mt][3] = __float_as_uint(As[kb + 4 + lr][mb + lq + 8]);
            }
#pragma unroll
            for (int nt = 0; nt < 4; nt++) {
                int nb = wn + nt * 8;
                b[nt][0] = __float_as_uint(Ws[kb + lr][nb + lq]);
                b[nt][1] = __float_as_uint(Ws[kb + 4 + lr][nb + lq]);
            }
#pragma unroll
            for (int mt = 0; mt < 2; mt++)
#pragma unroll
                for (int nt = 0; nt < 4; nt++)
                    mma_tf32(acc[mt][nt], a[mt][0], a[mt][1], a[mt][2], a[mt][3],
                             b[nt][0], b[nt][1]);
        }
        __syncthreads();
    }
#pragma unroll
    for (int mt = 0; mt < 2; mt++) {
#pragma unroll
        for (int nt = 0; nt < 4; nt++) {
            int gc = n0 + wn + nt * 8 + 2 * lr;
            float bi0 = bias ? bias[gc] : 0.f;
            float bi1 = bias ? bias[gc + 1] : 0.f;
#pragma unroll
            for (int half = 0; half < 2; half++) {
                int gr = m0 + wm + mt * 16 + lq + half * 8;
                float2 v;
                v.x = alpha * acc[mt][nt][half * 2] + bi0;
                v.y = alpha * acc[mt][nt][half * 2 + 1] + bi1;
                *reinterpret_cast<float2*>(&Cc[(size_t)gr * ldc + gc]) = v;
            }
        }
    }
}

// ---------------- row softmax in-place on [B*N, N] ----------------
__global__ void k_row_softmax(float* __restrict__ E) {
    size_t off = (size_t)blockIdx.x * NNODE;
    __shared__ float row[NNODE];
    __shared__ float sh[8];
    int tid = threadIdx.x;
    float lmax = -3.4e38f;
    for (int i = tid; i < NNODE; i += 256) {
        float v = E[off + i];
        row[i] = v;
        lmax = fmaxf(lmax, v);
    }
    float mx = blockMax(lmax, sh);
    float ls = 0.f;
    for (int i = tid; i < NNODE; i += 256) {
        float e = __expf(row[i] - mx);
        row[i] = e;
        ls += e;
    }
    float Z = blockSum(ls, sh);
    float invZ = 1.f / Z;
    for (int i = tid; i < NNODE; i += 256) E[off + i] = row[i] * invZ;
}

// ---------------- fused LN1 + graph-mix + LN2 ----------------
__global__ void k_ln_fuse(const float* __restrict__ node, const float* __restrict__ edge,
                          const float* __restrict__ s,
                          const float* __restrict__ g1, const float* __restrict__ b1,
                          const float* __restrict__ g2, const float* __restrict__ b2,
                          float* __restrict__ y) {
    int bn = blockIdx.x;
    int b = bn >> 10, n = bn & 1023;
    __shared__ float row[CC];
    __shared__ float sh[8];
    int tid = threadIdx.x;
    const float* xr = node + (size_t)bn * CC;
    float lsum = 0.f, lsq = 0.f;
    for (int c = tid; c < CC; c += 256) {
        float v = xr[c];
        row[c] = v;
        lsum += v;
        lsq += v * v;
    }
    float sum = blockSum(lsum, sh);
    float sq = blockSum(lsq, sh);
    float mean = sum * (1.f / CC);
    float var = sq * (1.f / CC) - mean * mean;
    float inv = rsqrtf(var + LN_EPS);
    float diag = edge[((size_t)b * NNODE + n) * NNODE + n];
    lsum = 0.f;
    lsq = 0.f;
    for (int c = tid; c < CC; c += 256) {
        float nt = (row[c] - mean) * inv * g1[c] + b1[c];
        float n2 = diag * nt * s[b * CC + c] + nt;
        row[c] = n2;
        lsum += n2;
        lsq += n2 * n2;
    }
    float sum2 = blockSum(lsum, sh);
    float sq2 = blockSum(lsq, sh);
    float mean2 = sum2 * (1.f / CC);
    float var2 = sq2 * (1.f / CC) - mean2 * mean2;
    float inv2 = rsqrtf(var2 + LN_EPS);
    float* yr = y + (size_t)bn * CC;
    for (int c = tid; c < CC; c += 256)
        yr[c] = (row[c] - mean2) * inv2 * g2[c] + b2[c];
}

// ================= fused attention per (16-row tile, head, batch) =================
// grid (N/16, NH, B) = 1024 blocks, 256 thr, ~90KB smem, 2 blocks/SM.
// S[16][1028] @0 (16448) ; Qh[40][24] @16448 (960) ; Ks[40][72]/Vs[128][40] union @17408 (5120)
#define FA2_SMEM_FLOATS 22528
__global__ void __launch_bounds__(256, 2)
k_fattn2(const float* __restrict__ qkv, const float* __restrict__ edge,
         float* __restrict__ nodeout, float* __restrict__ hbuf,
         const float* __restrict__ exp_w, const float* __restrict__ exp_b,
         const float* __restrict__ red_w) {
    extern __shared__ float sm[];
    float* S = sm;
    float* Qh = sm + 16448;
    float* Ks = sm + 17408;
    float* Vs = sm + 17408;
    int n0 = blockIdx.x * 16;
    int h = blockIdx.y;
    int b = blockIdx.z;
    int tid = threadIdx.x, warp = tid >> 5, lane = tid & 31;
    int lq = lane >> 2, lr = lane & 3;
    const float* qbase = qkv + (size_t)b * NNODE * C3;
    const float* erow = edge + ((size_t)b * NNODE + n0) * NNODE;

    // Q head tile -> Qh[d][r]
    for (int i = tid; i < 16 * DH; i += 256) {
        int r = i / DH, d = i - r * DH;
        Qh[d * 24 + r] = f2tf_f(qbase[(size_t)(n0 + r) * C3 + h * DH + d]);
    }
    float ew = exp_w[h], eb = exp_b[h];
    const float* kbase = qbase + CC + h * DH;

    // ---- logits: m-chunks of 64 ----
    for (int m0 = 0; m0 < NNODE; m0 += 64) {
        __syncthreads();
        for (int i = tid; i < 64 * DH; i += 256) {
            int j = i / DH, d = i - j * DH;
            Ks[d * 72 + j] = f2tf_f(kbase[(size_t)(m0 + j) * C3 + d]);
        }
        __syncthreads();
        float acc[4] = {};
        int nb = warp * 8;
#pragma unroll
        for (int ks = 0; ks < 5; ks++) {
            int kb = ks * 8;
            unsigned a0 = __float_as_uint(Qh[(kb + lr) * 24 + lq]);
            unsigned a1 = __float_as_uint(Qh[(kb + lr) * 24 + lq + 8]);
            unsigned a2 = __float_as_uint(Qh[(kb + 4 + lr) * 24 + lq]);
            unsigned a3 = __float_as_uint(Qh[(kb + 4 + lr) * 24 + lq + 8]);
            unsigned b0 = __float_as_uint(Ks[(kb + lr) * 72 + nb + lq]);
            unsigned b1 = __float_as_uint(Ks[(kb + 4 + lr) * 72 + nb + lq]);
            mma_tf32(acc, a0, a1, a2, a3, b0, b1);
        }
        int gc = m0 + nb + 2 * lr;
        float2 e0 = *reinterpret_cast<const float2*>(&erow[(size_t)lq * NNODE + gc]);
        float2 e1 = *reinterpret_cast<const float2*>(&erow[(size_t)(lq + 8) * NNODE + gc]);
        float2 v0, v1;
        v0.x = acc[0] * ATTN_SCALE + ew * e0.x + eb;
        v0.y = acc[1] * ATTN_SCALE + ew * e0.y + eb;
        v1.x = acc[2] * ATTN_SCALE + ew * e1.x + eb;
        v1.y = acc[3] * ATTN_SCALE + ew * e1.y + eb;
        *reinterpret_cast<float2*>(&S[lq * 1028 + gc]) = v0;
        *reinterpret_cast<float2*>(&S[(lq + 8) * 1028 + gc]) = v1;
    }
    __syncthreads();

    // ---- softmax + per-head ednew contribution: warp per 2 rows ----
    float rw = red_w[h];
#pragma unroll
    for (int rr = 0; rr < 2; rr++) {
        int r = warp * 2 + rr;
        float mx = -3.4e38f;
        for (int m = lane; m < NNODE; m += 32) mx = fmaxf(mx, S[r * 1028 + m]);
        mx = warpRedMax(mx);
        float sum = 0.f;
        for (int m = lane; m < NNODE; m += 32) sum += __expf(S[r * 1028 + m] - mx);
        sum = warpRedSum(sum);
        float invZ = 1.f / sum;
        float* edh = hbuf + (((size_t)(b * NH + h)) * NNODE + n0 + r) * NNODE;
        for (int m = lane; m < NNODE; m += 32) {
            float l = S[r * 1028 + m];
            float p = __expf(l - mx) * invZ;
            edh[m] = rw * (l + p);
            S[r * 1028 + m] = p;
        }
    }

    // ---- AV: warps 0..4, m-chunks of 128 ----
    float av[4] = {0.f, 0.f, 0.f, 0.f};
    const float* vbase = qbase + 2 * CC + h * DH;
    for (int mv0 = 0; mv0 < NNODE; mv0 += 128) {
        __syncthreads();
        for (int i = tid; i < 128 * DH; i += 256) {
            int j = i / DH, d = i - j * DH;
            Vs[j * 40 + d] = f2tf_f(vbase[(size_t)(mv0 + j) * C3 + d]);
        }
        __syncthreads();
        if (warp < 5) {
#pragma unroll
            for (int ks = 0; ks < 16; ks++) {
                int kb = ks * 8;
                unsigned a0 = __float_as_uint(S[lq * 1028 + mv0 + kb + lr]);
                unsigned a1 = __float_as_uint(S[(lq + 8) * 1028 + mv0 + kb + lr]);
                unsigned a2 = __float_as_uint(S[lq * 1028 + mv0 + kb + 4 + lr]);
                unsigned a3 = __float_as_uint(S[(lq + 8) * 1028 + mv0 + kb + 4 + lr]);
                unsigned b0 = __float_as_uint(Vs[(kb + lr) * 40 + warp * 8 + lq]);
                unsigned b1 = __float_as_uint(Vs[(kb + 4 + lr) * 40 + warp * 8 + lq]);
                mma_tf32(av, a0, a1, a2, a3, b0, b1);
            }
        }
    }
    if (warp < 5) {
        float* nbase = nodeout + ((size_t)b * NNODE + n0) * CC;
        int gc = h * DH + warp * 8 + 2 * lr;
        *reinterpret_cast<float2*>(&nbase[(size_t)lq * CC + gc]) =
            make_float2(av[0], av[1]);
        *reinterpret_cast<float2*>(&nbase[(size_t)(lq + 8) * CC + gc]) =
            make_float2(av[2], av[3]);
    }
}

// ------- per (b,n): en=sum_h hbuf+rb; wsum; edge+=en; node_out+=wsum -------
__global__ void k_edpost(float* __restrict__ edge, const float* __restrict__ hbuf,
                         float* __restrict__ nodeout, const float* __restrict__ red_b) {
    int bn = blockIdx.x;
    int b = bn >> 10, n = bn & 1023;
    __shared__ float row[NNODE];
    __shared__ float sh[8];
    int tid = threadIdx.x;
    float rb = red_b[0];
    const float* base = hbuf + ((size_t)b * NH * NNODE + n) * NNODE;
    float lmax = -3.4e38f;
    for (int i = tid; i < NNODE; i += 256) {
        float v = rb;
#pragma unroll
        for (int h = 0; h < NH; h++) v += base[(size_t)h * NNODE * NNODE + i];
        row[i] = v;
        lmax = fmaxf(lmax, v);
    }
    float mx = blockMax(lmax, sh);
    float ls = 0.f, lS = 0.f;
    for (int i = tid; i < NNODE; i += 256) {
        float v = row[i];
        float e = __expf(v - mx);
        ls += e;
        lS += e * v;
    }
    float Z = blockSum(ls, sh);
    float Ssum = blockSum(lS, sh);
    float wsum = Ssum / Z;
    float* eg = edge + (size_t)bn * NNODE;
    for (int i = tid; i < NNODE; i += 256) eg[i] += row[i];
    float* np = nodeout + (size_t)bn * CC;
    for (int c = tid; c < CC; c += 256) np[c] += wsum;
}

// ---------------- launch ----------------
extern "C" void kernel_launch(void* const* d_in, const int* in_sizes, int n_in,
                              void* d_out, int out_size) {
    const float* x = (const float*)d_in[0];
    const float* da_prior = (const float*)d_in[1];
    const float* qk_w = (const float*)d_in[2];
    const float* fcp_w = (const float*)d_in[3];
    const float* fcp_b = (const float*)d_in[4];
    const float* ln1_g = (const float*)d_in[5];
    const float* ln1_b = (const float*)d_in[6];
    const float* gln_g = (const float*)d_in[7];
    const float* gln_b = (const float*)d_in[8];
    const float* qkv_w = (const float*)d_in[9];
    const float* qkv_b = (const float*)d_in[10];
    const float* proj_w = (const float*)d_in[11];
    const float* proj_b = (const float*)d_in[12];
    const float* exp_w = (const float*)d_in[13];
    const float* exp_b = (const float*)d_in[14];
    const float* red_w = (const float*)d_in[15];
    const float* red_b = (const float*)d_in[16];
    float* out = (float*)d_out;

    float *p_node, *p_qk, *p_y, *p_qkv, *p_edge, *p_hbuf, *p_nodeout, *p_s;
    cudaGetSymbolAddress((void**)&p_node, g_node);
    cudaGetSymbolAddress((void**)&p_qk, g_qk);
    cudaGetSymbolAddress((void**)&p_y, g_y);
    cudaGetSymbolAddress((void**)&p_qkv, g_qkv);
    cudaGetSymbolAddress((void**)&p_edge, g_edge);
    cudaGetSymbolAddress((void**)&p_hbuf, g_hbuf);
    cudaGetSymbolAddress((void**)&p_nodeout, g_nodeout);
    cudaGetSymbolAddress((void**)&p_s, g_s);

    static const size_t fa_smem = FA2_SMEM_FLOATS * sizeof(float);
    cudaFuncSetAttribute(k_fattn2, cudaFuncAttributeMaxDynamicSharedMemorySize,
                         (int)fa_smem);

    k_tin<<<dim3(NNODE / 32, CC / 32, BB), dim3(32, 8)>>>(x, p_node);
    k_prior<<<3, 256>>>(da_prior, fcp_w, fcp_b, p_s);
    k_mm<<<dim3(C2 / 64, (BB * NNODE) / 128, 1), 256>>>(
        p_node, CC, 0, qk_w, CC, 0, p_qk, C2, 0, CC, 1.f, nullptr);
    k_mm<<<dim3(NNODE / 64, NNODE / 128, BB), 256>>>(
        p_qk, C2, (size_t)NNODE * C2, p_qk + CC, C2, (size_t)NNODE * C2,
        p_edge, NNODE, (size_t)NNODE * NNODE, CC, EDGE_SCALE, nullptr);
    k_row_softmax<<<BB * NNODE, 256>>>(p_edge);

    for (int l = 0; l < LLAYERS; l++) {
        k_ln_fuse<<<BB * NNODE, 256>>>(p_node, p_edge, p_s,
                                       ln1_g + l * CC, ln1_b + l * CC,
                                       gln_g + l * CC, gln_b + l * CC, p_y);
        k_mm<<<dim3(C3 / 64, (BB * NNODE) / 128, 1), 256>>>(
            p_y, CC, 0, qkv_w + (size_t)l * C3 * CC, CC, 0,
            p_qkv, C3, 0, CC, 1.f, qkv_b + l * C3);
        k_fattn2<<<dim3(NNODE / 16, NH, BB), 256, fa_smem>>>(
            p_qkv, p_edge, p_nodeout, p_hbuf, exp_w + l * NH, exp_b + l * NH,
            red_w + l * NH);
        k_edpost<<<BB * NNODE, 256>>>(p_edge, p_hbuf, p_nodeout, red_b + l);
        k_mm<<<dim3(CC / 64, (BB * NNODE) / 128, 1), 256>>>(
            p_nodeout, CC, 0, proj_w + (size_t)l * CC * CC, CC, 0,
            p_node, CC, 0, CC, 1.f, proj_b + l * CC);
    }

    k_tout<<<dim3(NNODE / 32, CC / 32, BB), dim3(32, 8)>>>(p_node, out);
}

// round 9
// speedup vs baseline: 2.2808x; 1.6192x over previous
#include <cuda_runtime.h>
#include <math.h>

// ---------------- problem constants ----------------
#define BB   2
#define CC   320
#define NNODE 1024
#define NH   8
#define DH   40
#define LLAYERS 2
#define C2   640
#define C3   960
#define AA   16
#define EPD  64

#define EDGE_SCALE 0.17677669529663687f  // 32^-0.5
#define ATTN_SCALE 0.15811388300841897f  // 40^-0.5
#define LN_EPS 1e-5f

// ---------------- scratch ----------------
static __device__ float g_node[BB * NNODE * CC];
static __device__ float g_qk[BB * NNODE * C2];
static __device__ float g_y[BB * NNODE * CC];
static __device__ float g_qkv[BB * NNODE * C3];
static __device__ float g_edge[BB * NNODE * NNODE];
static __device__ float g_hbuf[(size_t)BB * NH * NNODE * NNODE];
static __device__ float g_nodeout[BB * NNODE * CC];
static __device__ float g_s[BB * CC];

// ---------------- tf32 / mma helpers ----------------
__device__ __forceinline__ unsigned f2tf(float f) {
    unsigned r;
    asm("cvt.rna.tf32.f32 %0, %1;" : "=r"(r) : "f"(f));
    return r;
}
__device__ __forceinline__ float f2tf_f(float f) {
    return __uint_as_float(f2tf(f));
}
__device__ __forceinline__ void mma_tf32(float (&c)[4], unsigned a0, unsigned a1,
                                         unsigned a2, unsigned a3, unsigned b0,
                                         unsigned b1) {
    asm volatile(
        "mma.sync.aligned.m16n8k8.row.col.f32.tf32.tf32.f32 "
        "{%0,%1,%2,%3},{%4,%5,%6,%7},{%8,%9},{%0,%1,%2,%3};"
        : "+f"(c[0]), "+f"(c[1]), "+f"(c[2]), "+f"(c[3])
        : "r"(a0), "r"(a1), "r"(a2), "r"(a3), "r"(b0), "r"(b1));
}

// ---------------- cp.async helpers ----------------
__device__ __forceinline__ void cp16(float* smem, const float* g) {
    unsigned s = (unsigned)__cvta_generic_to_shared(smem);
    asm volatile("cp.async.ca.shared.global [%0], [%1], 16;" :: "r"(s), "l"(g));
}
__device__ __forceinline__ void cpcommit() {
    asm volatile("cp.async.commit_group;");
}
__device__ __forceinline__ void cpwait0() {
    asm volatile("cp.async.wait_group 0;");
}
__device__ __forceinline__ void cpwait1() {
    asm volatile("cp.async.wait_group 1;");
}

// ---------------- reductions ----------------
__device__ __forceinline__ float warpRedSum(float v) {
#pragma unroll
    for (int o = 16; o; o >>= 1) v += __shfl_xor_sync(0xffffffffu, v, o);
    return v;
}
__device__ __forceinline__ float warpRedMax(float v) {
#pragma unroll
    for (int o = 16; o; o >>= 1) v = fmaxf(v, __shfl_xor_sync(0xffffffffu, v, o));
    return v;
}
__device__ __forceinline__ float blockSum(float v, float* sh) {
    v = warpRedSum(v);
    if ((threadIdx.x & 31) == 0) sh[threadIdx.x >> 5] = v;
    __syncthreads();
    float r = sh[0];
#pragma unroll
    for (int i = 1; i < 8; i++) r += sh[i];
    __syncthreads();
    return r;
}
__device__ __forceinline__ float blockMax(float v, float* sh) {
    v = warpRedMax(v);
    if ((threadIdx.x & 31) == 0) sh[threadIdx.x >> 5] = v;
    __syncthreads();
    float r = sh[0];
#pragma unroll
    for (int i = 1; i < 8; i++) r = fmaxf(r, sh[i]);
    __syncthreads();
    return r;
}

// ---------------- transposes ----------------
__global__ void k_tin(const float* __restrict__ x, float* __restrict__ node) {
    __shared__ float t[32][33];
    int b = blockIdx.z;
    int c0 = blockIdx.y * 32, n0 = blockIdx.x * 32;
#pragma unroll
    for (int i = 0; i < 4; i++)
        t[threadIdx.y + i * 8][threadIdx.x] =
            x[((size_t)b * CC + c0 + threadIdx.y + i * 8) * NNODE + n0 + threadIdx.x];
    __syncthreads();
#pragma unroll
    for (int i = 0; i < 4; i++)
        node[((size_t)b * NNODE + n0 + threadIdx.y + i * 8) * CC + c0 + threadIdx.x] =
            t[threadIdx.x][threadIdx.y + i * 8];
}

__global__ void k_tout(const float* __restrict__ node, float* __restrict__ out) {
    __shared__ float t[32][33];
    int b = blockIdx.z;
    int c0 = blockIdx.y * 32, n0 = blockIdx.x * 32;
#pragma unroll
    for (int i = 0; i < 4; i++)
        t[threadIdx.y + i * 8][threadIdx.x] =
            node[((size_t)b * NNODE + n0 + threadIdx.y + i * 8) * CC + c0 + threadIdx.x];
    __syncthreads();
#pragma unroll
    for (int i = 0; i < 4; i++)
        out[((size_t)b * CC + c0 + threadIdx.y + i * 8) * NNODE + n0 + threadIdx.x] =
            t[threadIdx.x][threadIdx.y + i * 8];
}

// ---------------- prior sum ----------------
__global__ void k_prior(const float* __restrict__ da, const float* __restrict__ w,
                        const float* __restrict__ bfc, float* __restrict__ s) {
    int t = blockIdx.x * blockDim.x + threadIdx.x;
    if (t >= BB * CC) return;
    int b = t / CC, c = t % CC;
    float acc = (float)AA * bfc[c];
    for (int e = 0; e < EPD; e++) {
        float sa = 0.f;
#pragma unroll
        for (int a = 0; a < AA; a++) sa += da[((size_t)b * AA + a) * EPD + e];
        acc += sa * w[c * EPD + e];
    }
    s[t] = acc;
}

// ============ tf32 NT GEMM, cp.async double-buffered ============
// tile 128x64, 8 warps (4m x 2n), warp 32x32, TK=16.
// Row-major smem tiles, pitch 20 floats (80B): conflict-free fragment loads.
__global__ void __launch_bounds__(256) k_mm(
    const float* __restrict__ A, int lda, size_t sA,
    const float* __restrict__ W, int ldw, size_t sW,
    float* __restrict__ Cc, int ldc, size_t sC, int K, float alpha,
    const float* __restrict__ bias) {
    int bz = blockIdx.z;
    A += (size_t)bz * sA;
    W += (size_t)bz * sW;
    Cc += (size_t)bz * sC;
    __shared__ float As[2][128 * 20];
    __shared__ float Ws[2][64 * 20];
    int m0 = blockIdx.y * 128, n0 = blockIdx.x * 64;
    int tid = threadIdx.x;
    int warp = tid >> 5, lane = tid & 31;
    int wm = (warp >> 1) * 32, wn = (warp & 1) * 32;
    int lq = lane >> 2, lr = lane & 3;
    float acc[2][4][4] = {};

    // stage tile (k0) into buffer buf
    auto stage = [&](int buf, int k0) {
#pragma unroll
        for (int i = 0; i < 2; i++) {
            int idx = tid + i * 256;  // 512 A segs (128 rows x 4)
            int r = idx >> 2, sg = idx & 3;
            cp16(&As[buf][r * 20 + sg * 4], &A[(size_t)(m0 + r) * lda + k0 + sg * 4]);
        }
        {
            int r = tid >> 2, sg = tid & 3;  // 256 W segs (64 rows x 4)
            cp16(&Ws[buf][r * 20 + sg * 4], &W[(size_t)(n0 + r) * ldw + k0 + sg * 4]);
        }
    };

    stage(0, 0);
    cpcommit();
    int nk = K / 16;
    for (int kc = 0; kc < nk; kc++) {
        if (kc + 1 < nk) {
            stage((kc + 1) & 1, (kc + 1) * 16);
            cpcommit();
            cpwait1();
        } else {
            cpwait0();
        }
        __syncthreads();
        const float* Ab = As[kc & 1];
        const float* Wb = Ws[kc & 1];
#pragma unroll
        for (int kh = 0; kh < 2; kh++) {
            int kb = kh * 8;
            unsigned a[2][4], b[4][2];
#pragma unroll
            for (int mt = 0; mt < 2; mt++) {
                int mb = wm + mt * 16;
                a[mt][0] = f2tf(Ab[(mb + lq) * 20 + kb + lr]);
                a[mt][1] = f2tf(Ab[(mb + lq + 8) * 20 + kb + lr]);
                a[mt][2] = f2tf(Ab[(mb + lq) * 20 + kb + 4 + lr]);
                a[mt][3] = f2tf(Ab[(mb + lq + 8) * 20 + kb + 4 + lr]);
            }
#pragma unroll
            for (int nt = 0; nt < 4; nt++) {
                int nb = wn + nt * 8;
                b[nt][0] = f2tf(Wb[(nb + lq) * 20 + kb + lr]);
                b[nt][1] = f2tf(Wb[(nb + lq) * 20 + kb + 4 + lr]);
            }
#pragma unroll
            for (int mt = 0; mt < 2; mt++)
#pragma unroll
                for (int nt = 0; nt < 4; nt++)
                    mma_tf32(acc[mt][nt], a[mt][0], a[mt][1], a[mt][2], a[mt][3],
                             b[nt][0], b[nt][1]);
        }
        __syncthreads();
    }
#pragma unroll
    for (int mt = 0; mt < 2; mt++) {
#pragma unroll
        for (int nt = 0; nt < 4; nt++) {
            int gc = n0 + wn + nt * 8 + 2 * lr;
            float bi0 = bias ? bias[gc] : 0.f;
            float bi1 = bias ? bias[gc + 1] : 0.f;
#pragma unroll
            for (int half = 0; half < 2; half++) {
                int gr = m0 + wm + mt * 16 + lq + half * 8;
                float2 v;
                v.x = alpha * acc[mt][nt][half * 2] + bi0;
                v.y = alpha * acc[mt][nt][half * 2 + 1] + bi1;
                *reinterpret_cast<float2*>(&Cc[(size_t)gr * ldc + gc]) = v;
            }
        }
    }
}

// ---------------- row softmax in-place on [B*N, N] ----------------
__global__ void k_row_softmax(float* __restrict__ E) {
    size_t off = (size_t)blockIdx.x * NNODE;
    __shared__ float row[NNODE];
    __shared__ float sh[8];
    int tid = threadIdx.x;
    float lmax = -3.4e38f;
    for (int i = tid; i < NNODE; i += 256) {
        float v = E[off + i];
        row[i] = v;
        lmax = fmaxf(lmax, v);
    }
    float mx = blockMax(lmax, sh);
    float ls = 0.f;
    for (int i = tid; i < NNODE; i += 256) {
        float e = __expf(row[i] - mx);
        row[i] = e;
        ls += e;
    }
    float Z = blockSum(ls, sh);
    float invZ = 1.f / Z;
    for (int i = tid; i < NNODE; i += 256) E[off + i] = row[i] * invZ;
}

// ---------------- fused LN1 + graph-mix + LN2 ----------------
__global__ void k_ln_fuse(const float* __restrict__ node, const float* __restrict__ edge,
                          const float* __restrict__ s,
                          const float* __restrict__ g1, const float* __restrict__ b1,
                          const float* __restrict__ g2, const float* __restrict__ b2,
                          float* __restrict__ y) {
    int bn = blockIdx.x;
    int b = bn >> 10, n = bn & 1023;
    __shared__ float row[CC];
    __shared__ float sh[8];
    int tid = threadIdx.x;
    const float* xr = node + (size_t)bn * CC;
    float lsum = 0.f, lsq = 0.f;
    for (int c = tid; c < CC; c += 256) {
        float v = xr[c];
        row[c] = v;
        lsum += v;
        lsq += v * v;
    }
    float sum = blockSum(lsum, sh);
    float sq = blockSum(lsq, sh);
    float mean = sum * (1.f / CC);
    float var = sq * (1.f / CC) - mean * mean;
    float inv = rsqrtf(var + LN_EPS);
    float diag = edge[((size_t)b * NNODE + n) * NNODE + n];
    lsum = 0.f;
    lsq = 0.f;
    for (int c = tid; c < CC; c += 256) {
        float nt = (row[c] - mean) * inv * g1[c] + b1[c];
        float n2 = diag * nt * s[b * CC + c] + nt;
        row[c] = n2;
        lsum += n2;
        lsq += n2 * n2;
    }
    float sum2 = blockSum(lsum, sh);
    float sq2 = blockSum(lsq, sh);
    float mean2 = sum2 * (1.f / CC);
    float var2 = sq2 * (1.f / CC) - mean2 * mean2;
    float inv2 = rsqrtf(var2 + LN_EPS);
    float* yr = y + (size_t)bn * CC;
    for (int c = tid; c < CC; c += 256)
        yr[c] = (row[c] - mean2) * inv2 * g2[c] + b2[c];
}

// ================= fused attention per (16-row tile, head, batch) =================
// grid (N/16, NH, B) = 1024 blocks, 256 thr.
// smem (floats): S[16][1028] @0 (16448) ; Qh[40][24] @16448 (960)
//                union @17408: K double 2x64x44 (5632) / V double 2x128x44 (11264)
// total = 28672 floats = 112 KB -> 2 blocks/SM.
#define FA_SMEM_FLOATS 28672
__global__ void __launch_bounds__(256, 2)
k_fattn2(const float* __restrict__ qkv, const float* __restrict__ edge,
         float* __restrict__ nodeout, float* __restrict__ hbuf,
         const float* __restrict__ exp_w, const float* __restrict__ exp_b,
         const float* __restrict__ red_w) {
    extern __shared__ float sm[];
    float* S = sm;
    float* Qh = sm + 16448;
    float* U = sm + 17408;  // staging union
    int n0 = blockIdx.x * 16;
    int h = blockIdx.y;
    int b = blockIdx.z;
    int tid = threadIdx.x, warp = tid >> 5, lane = tid & 31;
    int lq = lane >> 2, lr = lane & 3;
    const float* qbase = qkv + (size_t)b * NNODE * C3;
    const float* kbase = qbase + CC + h * DH;
    const float* vbase = qbase + 2 * CC + h * DH;
    const float* erow = edge + ((size_t)b * NNODE + n0) * NNODE;

    // K chunk (64 rows x 40 floats, pitch 44) via cp.async
    auto stageK = [&](float* buf, int m0) {
#pragma unroll
        for (int i = 0; i < 3; i++) {
            int idx = tid + i * 256;
            if (idx < 640) {
                int r = idx / 10, sg = idx - r * 10;
                cp16(&buf[r * 44 + sg * 4], kbase + (size_t)(m0 + r) * C3 + sg * 4);
            }
        }
    };
    // V chunk (128 rows x 40 floats, pitch 44) via cp.async
    auto stageV = [&](float* buf, int m0) {
#pragma unroll
        for (int i = 0; i < 5; i++) {
            int idx = tid + i * 256;
            int r = idx / 10, sg = idx - r * 10;
            cp16(&buf[r * 44 + sg * 4], vbase + (size_t)(m0 + r) * C3 + sg * 4);
        }
    };

    // Q head tile -> Qh[d][r] (pre-converted)
    for (int i = tid; i < 16 * DH; i += 256) {
        int r = i / DH, d = i - r * DH;
        Qh[d * 24 + r] = f2tf_f(qbase[(size_t)(n0 + r) * C3 + h * DH + d]);
    }
    float ew = exp_w[h], eb = exp_b[h];

    // ---- logits: 16 chunks of 64 cols, double-buffered K staging ----
    stageK(U, 0);
    cpcommit();
    for (int c = 0; c < 16; c++) {
        if (c + 1 < 16) {
            stageK(U + ((c + 1) & 1) * 2816, (c + 1) * 64);
            cpcommit();
            cpwait1();
        } else {
            cpwait0();
        }
        __syncthreads();
        const float* Kb = U + (c & 1) * 2816;
        float acc[4] = {};
        int nb = warp * 8;
#pragma unroll
        for (int ks = 0; ks < 5; ks++) {
            int kb = ks * 8;
            unsigned a0 = __float_as_uint(Qh[(kb + lr) * 24 + lq]);
            unsigned a1 = __float_as_uint(Qh[(kb + lr) * 24 + lq + 8]);
            unsigned a2 = __float_as_uint(Qh[(kb + 4 + lr) * 24 + lq]);
            unsigned a3 = __float_as_uint(Qh[(kb + 4 + lr) * 24 + lq + 8]);
            unsigned b0 = f2tf(Kb[(nb + lq) * 44 + kb + lr]);
            unsigned b1 = f2tf(Kb[(nb + lq) * 44 + kb + 4 + lr]);
            mma_tf32(acc, a0, a1, a2, a3, b0, b1);
        }
        int gc = c * 64 + nb + 2 * lr;
        float2 e0 = *reinterpret_cast<const float2*>(&erow[(size_t)lq * NNODE + gc]);
        float2 e1 =
            *reinterpret_cast<const float2*>(&erow[(size_t)(lq + 8) * NNODE + gc]);
        float2 v0, v1;
        v0.x = acc[0] * ATTN_SCALE + ew * e0.x + eb;
        v0.y = acc[1] * ATTN_SCALE + ew * e0.y + eb;
        v1.x = acc[2] * ATTN_SCALE + ew * e1.x + eb;
        v1.y = acc[3] * ATTN_SCALE + ew * e1.y + eb;
        *reinterpret_cast<float2*>(&S[lq * 1028 + gc]) = v0;
        *reinterpret_cast<float2*>(&S[(lq + 8) * 1028 + gc]) = v1;
        __syncthreads();
    }

    // prefetch first V chunk, overlapped with softmax
    stageV(U, 0);
    cpcommit();

    // ---- softmax + per-head ednew contribution (single exp, logits in regs) ----
    float rw = red_w[h];
    float* edh_base = hbuf + (((size_t)(b * NH + h)) * NNODE + n0) * NNODE;
#pragma unroll
    for (int rr = 0; rr < 2; rr++) {
        int r = warp * 2 + rr;
        float l[32];
        float mx = -3.4e38f;
#pragma unroll
        for (int k = 0; k < 32; k++) {
            l[k] = S[r * 1028 + k * 32 + lane];
            mx = fmaxf(mx, l[k]);
        }
        mx = warpRedMax(mx);
        float sum = 0.f;
#pragma unroll
        for (int k = 0; k < 32; k++) {
            float e = __expf(l[k] - mx);
            S[r * 1028 + k * 32 + lane] = e;
            sum += e;
        }
        sum = warpRedSum(sum);
        float invZ = 1.f / sum;
        float* edh = edh_base + (size_t)r * NNODE;
#pragma unroll
        for (int k = 0; k < 32; k++) {
            float p = S[r * 1028 + k * 32 + lane] * invZ;
            S[r * 1028 + k * 32 + lane] = p;
            edh[k * 32 + lane] = rw * (l[k] + p);
        }
    }

    // ---- AV: 8 chunks of 128, double-buffered V staging; warps 0..4 compute ----
    float av[4] = {0.f, 0.f, 0.f, 0.f};
    for (int c = 0; c < 8; c++) {
        if (c + 1 < 8) {
            stageV(U + ((c + 1) & 1) * 5632, (c + 1) * 128);
            cpcommit();
            cpwait1();
        } else {
            cpwait0();
        }
        __syncthreads();
        const float* Vb = U + (c & 1) * 5632;
        int mv0 = c * 128;
        if (warp < 5) {
#pragma unroll
            for (int ks = 0; ks < 16; ks++) {
                int kb = ks * 8;
                unsigned a0 = f2tf(S[lq * 1028 + mv0 + kb + lr]);
                unsigned a1 = f2tf(S[(lq + 8) * 1028 + mv0 + kb + lr]);
                unsigned a2 = f2tf(S[lq * 1028 + mv0 + kb + 4 + lr]);
                unsigned a3 = f2tf(S[(lq + 8) * 1028 + mv0 + kb + 4 + lr]);
                unsigned b0 = f2tf(Vb[(kb + lr) * 44 + warp * 8 + lq]);
                unsigned b1 = f2tf(Vb[(kb + 4 + lr) * 44 + warp * 8 + lq]);
                mma_tf32(av, a0, a1, a2, a3, b0, b1);
            }
        }
        __syncthreads();
    }
    if (warp < 5) {
        float* nbase = nodeout + ((size_t)b * NNODE + n0) * CC;
        int gc = h * DH + warp * 8 + 2 * lr;
        *reinterpret_cast<float2*>(&nbase[(size_t)lq * CC + gc]) =
            make_float2(av[0], av[1]);
        *reinterpret_cast<float2*>(&nbase[(size_t)(lq + 8) * CC + gc]) =
            make_float2(av[2], av[3]);
    }
}

// ------- per (b,n): en=sum_h hbuf+rb; wsum; edge+=en; node_out+=wsum -------
__global__ void k_edpost(float* __restrict__ edge, const float* __restrict__ hbuf,
                         float* __restrict__ nodeout, const float* __restrict__ red_b) {
    int bn = blockIdx.x;
    int b = bn >> 10, n = bn & 1023;
    __shared__ float row[NNODE];
    __shared__ float sh[8];
    int tid = threadIdx.x;
    float rb = red_b[0];
    const float* base = hbuf + ((size_t)b * NH * NNODE + n) * NNODE;
    float lmax = -3.4e38f;
    for (int i = tid; i < NNODE; i += 256) {
        float v = rb;
#pragma unroll
        for (int h = 0; h < NH; h++) v += base[(size_t)h * NNODE * NNODE + i];
        row[i] = v;
        lmax = fmaxf(lmax, v);
    }
    float mx = blockMax(lmax, sh);
    float ls = 0.f, lS = 0.f;
    for (int i = tid; i < NNODE; i += 256) {
        float v = row[i];
        float e = __expf(v - mx);
        ls += e;
        lS += e * v;
    }
    float Z = blockSum(ls, sh);
    float Ssum = blockSum(lS, sh);
    float wsum = Ssum / Z;
    float* eg = edge + (size_t)bn * NNODE;
    for (int i = tid; i < NNODE; i += 256) eg[i] += row[i];
    float* np = nodeout + (size_t)bn * CC;
    for (int c = tid; c < CC; c += 256) np[c] += wsum;
}

// ---------------- launch ----------------
extern "C" void kernel_launch(void* const* d_in, const int* in_sizes, int n_in,
                              void* d_out, int out_size) {
    const float* x = (const float*)d_in[0];
    const float* da_prior = (const float*)d_in[1];
    const float* qk_w = (const float*)d_in[2];
    const float* fcp_w = (const float*)d_in[3];
    const float* fcp_b = (const float*)d_in[4];
    const float* ln1_g = (const float*)d_in[5];
    const float* ln1_b = (const float*)d_in[6];
    const float* gln_g = (const float*)d_in[7];
    const float* gln_b = (const float*)d_in[8];
    const float* qkv_w = (const float*)d_in[9];
    const float* qkv_b = (const float*)d_in[10];
    const float* proj_w = (const float*)d_in[11];
    const float* proj_b = (const float*)d_in[12];
    const float* exp_w = (const float*)d_in[13];
    const float* exp_b = (const float*)d_in[14];
    const float* red_w = (const float*)d_in[15];
    const float* red_b = (const float*)d_in[16];
    float* out = (float*)d_out;

    float *p_node, *p_qk, *p_y, *p_qkv, *p_edge, *p_hbuf, *p_nodeout, *p_s;
    cudaGetSymbolAddress((void**)&p_node, g_node);
    cudaGetSymbolAddress((void**)&p_qk, g_qk);
    cudaGetSymbolAddress((void**)&p_y, g_y);
    cudaGetSymbolAddress((void**)&p_qkv, g_qkv);
    cudaGetSymbolAddress((void**)&p_edge, g_edge);
    cudaGetSymbolAddress((void**)&p_hbuf, g_hbuf);
    cudaGetSymbolAddress((void**)&p_nodeout, g_nodeout);
    cudaGetSymbolAddress((void**)&p_s, g_s);

    static const size_t fa_smem = FA_SMEM_FLOATS * sizeof(float);
    cudaFuncSetAttribute(k_fattn2, cudaFuncAttributeMaxDynamicSharedMemorySize,
                         (int)fa_smem);

    k_tin<<<dim3(NNODE / 32, CC / 32, BB), dim3(32, 8)>>>(x, p_node);
    k_prior<<<3, 256>>>(da_prior, fcp_w, fcp_b, p_s);
    k_mm<<<dim3(C2 / 64, (BB * NNODE) / 128, 1), 256>>>(
        p_node, CC, 0, qk_w, CC, 0, p_qk, C2, 0, CC, 1.f, nullptr);
    k_mm<<<dim3(NNODE / 64, NNODE / 128, BB), 256>>>(
        p_qk, C2, (size_t)NNODE * C2, p_qk + CC, C2, (size_t)NNODE * C2,
        p_edge, NNODE, (size_t)NNODE * NNODE, CC, EDGE_SCALE, nullptr);
    k_row_softmax<<<BB * NNODE, 256>>>(p_edge);

    for (int l = 0; l < LLAYERS; l++) {
        k_ln_fuse<<<BB * NNODE, 256>>>(p_node, p_edge, p_s,
                                       ln1_g + l * CC, ln1_b + l * CC,
                                       gln_g + l * CC, gln_b + l * CC, p_y);
        k_mm<<<dim3(C3 / 64, (BB * NNODE) / 128, 1), 256>>>(
            p_y, CC, 0, qkv_w + (size_t)l * C3 * CC, CC, 0,
            p_qkv, C3, 0, CC, 1.f, qkv_b + l * C3);
        k_fattn2<<<dim3(NNODE / 16, NH, BB), 256, fa_smem>>>(
            p_qkv, p_edge, p_nodeout, p_hbuf, exp_w + l * NH, exp_b + l * NH,
            red_w + l * NH);
        k_edpost<<<BB * NNODE, 256>>>(p_edge, p_hbuf, p_nodeout, red_b + l);
        k_mm<<<dim3(CC / 64, (BB * NNODE) / 128, 1), 256>>>(
            p_nodeout, CC, 0, proj_w + (size_t)l * CC * CC, CC, 0,
            p_node, CC, 0, CC, 1.f, proj_b + l * CC);
    }

    k_tout<<<dim3(NNODE / 32, CC / 32, BB), dim3(32, 8)>>>(p_node, out);
}

// round 11
// speedup vs baseline: 2.3704x; 1.0393x over previous
#include <cuda_runtime.h>
#include <math.h>

// ---------------- problem constants ----------------
#define BB   2
#define CC   320
#define NNODE 1024
#define NH   8
#define DH   40
#define LLAYERS 2
#define C2   640
#define C3   960
#define AA   16
#define EPD  64

#define EDGE_SCALE 0.17677669529663687f  // 32^-0.5
#define ATTN_SCALE 0.15811388300841897f  // 40^-0.5
#define LN_EPS 1e-5f

// ---------------- scratch ----------------
static __device__ float g_node[BB * NNODE * CC];
static __device__ float g_qk[BB * NNODE * C2];
static __device__ float g_y[BB * NNODE * CC];
static __device__ float g_qkv[BB * NNODE * C3];
static __device__ float g_edge[BB * NNODE * NNODE];
static __device__ float g_hbuf[(size_t)BB * NH * NNODE * NNODE];
static __device__ float g_nodeout[BB * NNODE * CC];
static __device__ float g_s[BB * CC];

// ---------------- tf32 / mma helpers ----------------
__device__ __forceinline__ unsigned f2tf(float f) {
    unsigned r;
    asm("cvt.rna.tf32.f32 %0, %1;" : "=r"(r) : "f"(f));
    return r;
}
__device__ __forceinline__ float f2tf_f(float f) {
    return __uint_as_float(f2tf(f));
}
__device__ __forceinline__ void mma_tf32(float (&c)[4], unsigned a0, unsigned a1,
                                         unsigned a2, unsigned a3, unsigned b0,
                                         unsigned b1) {
    asm volatile(
        "mma.sync.aligned.m16n8k8.row.col.f32.tf32.tf32.f32 "
        "{%0,%1,%2,%3},{%4,%5,%6,%7},{%8,%9},{%0,%1,%2,%3};"
        : "+f"(c[0]), "+f"(c[1]), "+f"(c[2]), "+f"(c[3])
        : "r"(a0), "r"(a1), "r"(a2), "r"(a3), "r"(b0), "r"(b1));
}

// ---------------- cp.async helpers ----------------
__device__ __forceinline__ void cp16(float* smem, const float* g) {
    unsigned s = (unsigned)__cvta_generic_to_shared(smem);
    asm volatile("cp.async.ca.shared.global [%0], [%1], 16;" :: "r"(s), "l"(g));
}
__device__ __forceinline__ void cpcommit() {
    asm volatile("cp.async.commit_group;");
}
__device__ __forceinline__ void cpwait0() {
    asm volatile("cp.async.wait_group 0;");
}
__device__ __forceinline__ void cpwait1() {
    asm volatile("cp.async.wait_group 1;");
}

// ---------------- reductions ----------------
__device__ __forceinline__ float warpRedSum(float v) {
#pragma unroll
    for (int o = 16; o; o >>= 1) v += __shfl_xor_sync(0xffffffffu, v, o);
    return v;
}
__device__ __forceinline__ float warpRedMax(float v) {
#pragma unroll
    for (int o = 16; o; o >>= 1) v = fmaxf(v, __shfl_xor_sync(0xffffffffu, v, o));
    return v;
}
__device__ __forceinline__ float blockSum(float v, float* sh) {
    v = warpRedSum(v);
    if ((threadIdx.x & 31) == 0) sh[threadIdx.x >> 5] = v;
    __syncthreads();
    float r = sh[0];
#pragma unroll
    for (int i = 1; i < 8; i++) r += sh[i];
    __syncthreads();
    return r;
}
__device__ __forceinline__ float blockMax(float v, float* sh) {
    v = warpRedMax(v);
    if ((threadIdx.x & 31) == 0) sh[threadIdx.x >> 5] = v;
    __syncthreads();
    float r = sh[0];
#pragma unroll
    for (int i = 1; i < 8; i++) r = fmaxf(r, sh[i]);
    __syncthreads();
    return r;
}

// ---------------- transposes ----------------
__global__ void k_tin(const float* __restrict__ x, float* __restrict__ node) {
    __shared__ float t[32][33];
    int b = blockIdx.z;
    int c0 = blockIdx.y * 32, n0 = blockIdx.x * 32;
#pragma unroll
    for (int i = 0; i < 4; i++)
        t[threadIdx.y + i * 8][threadIdx.x] =
            x[((size_t)b * CC + c0 + threadIdx.y + i * 8) * NNODE + n0 + threadIdx.x];
    __syncthreads();
#pragma unroll
    for (int i = 0; i < 4; i++)
        node[((size_t)b * NNODE + n0 + threadIdx.y + i * 8) * CC + c0 + threadIdx.x] =
            t[threadIdx.x][threadIdx.y + i * 8];
}

__global__ void k_tout(const float* __restrict__ node, float* __restrict__ out) {
    __shared__ float t[32][33];
    int b = blockIdx.z;
    int c0 = blockIdx.y * 32, n0 = blockIdx.x * 32;
#pragma unroll
    for (int i = 0; i < 4; i++)
        t[threadIdx.y + i * 8][threadIdx.x] =
            node[((size_t)b * NNODE + n0 + threadIdx.y + i * 8) * CC + c0 + threadIdx.x];
    __syncthreads();
#pragma unroll
    for (int i = 0; i < 4; i++)
        out[((size_t)b * CC + c0 + threadIdx.y + i * 8) * NNODE + n0 + threadIdx.x] =
            t[threadIdx.x][threadIdx.y + i * 8];
}

// ---------------- prior sum ----------------
__global__ void k_prior(const float* __restrict__ da, const float* __restrict__ w,
                        const float* __restrict__ bfc, float* __restrict__ s) {
    int t = blockIdx.x * blockDim.x + threadIdx.x;
    if (t >= BB * CC) return;
    int b = t / CC, c = t % CC;
    float acc = (float)AA * bfc[c];
    for (int e = 0; e < EPD; e++) {
        float sa = 0.f;
#pragma unroll
        for (int a = 0; a < AA; a++) sa += da[((size_t)b * AA + a) * EPD + e];
        acc += sa * w[c * EPD + e];
    }
    s[t] = acc;
}

// ============ tf32 NT GEMM, 64x64 tile, 128 thr (4 warps 2x2, warp 32x32) ============
// cp.async double-buffered, row-major smem pitch 20 floats (conflict-free).
__global__ void __launch_bounds__(128) k_mm(
    const float* __restrict__ A, int lda, size_t sA,
    const float* __restrict__ W, int ldw, size_t sW,
    float* __restrict__ Cc, int ldc, size_t sC, int K, float alpha,
    const float* __restrict__ bias) {
    int bz = blockIdx.z;
    A += (size_t)bz * sA;
    W += (size_t)bz * sW;
    Cc += (size_t)bz * sC;
    __shared__ float As[2][64 * 20];
    __shared__ float Ws[2][64 * 20];
    int m0 = blockIdx.y * 64, n0 = blockIdx.x * 64;
    int tid = threadIdx.x;
    int warp = tid >> 5, lane = tid & 31;
    int wm = (warp >> 1) * 32, wn = (warp & 1) * 32;
    int lq = lane >> 2, lr = lane & 3;
    float acc[2][4][4] = {};

    auto stage = [&](int buf, int k0) {
#pragma unroll
        for (int i = 0; i < 2; i++) {
            int idx = tid + i * 128;
            int r = idx >> 2, sg = idx & 3;
            cp16(&As[buf][r * 20 + sg * 4], &A[(size_t)(m0 + r) * lda + k0 + sg * 4]);
        }
#pragma unroll
        for (int i = 0; i < 2; i++) {
            int idx = tid + i * 128;
            int r = idx >> 2, sg = idx & 3;
            cp16(&Ws[buf][r * 20 + sg * 4], &W[(size_t)(n0 + r) * ldw + k0 + sg * 4]);
        }
    };

    stage(0, 0);
    cpcommit();
    int nk = K / 16;
    for (int kc = 0; kc < nk; kc++) {
        if (kc + 1 < nk) {
            stage((kc + 1) & 1, (kc + 1) * 16);
            cpcommit();
            cpwait1();
        } else {
            cpwait0();
        }
        __syncthreads();
        const float* Ab = As[kc & 1];
        const float* Wb = Ws[kc & 1];
#pragma unroll
        for (int kh = 0; kh < 2; kh++) {
            int kb = kh * 8;
            unsigned a[2][4], b[4][2];
#pragma unroll
            for (int mt = 0; mt < 2; mt++) {
                int mb = wm + mt * 16;
                a[mt][0] = f2tf(Ab[(mb + lq) * 20 + kb + lr]);
                a[mt][1] = f2tf(Ab[(mb + lq + 8) * 20 + kb + lr]);
                a[mt][2] = f2tf(Ab[(mb + lq) * 20 + kb + 4 + lr]);
                a[mt][3] = f2tf(Ab[(mb + lq + 8) * 20 + kb + 4 + lr]);
            }
#pragma unroll
            for (int nt = 0; nt < 4; nt++) {
                int nb = wn + nt * 8;
                b[nt][0] = f2tf(Wb[(nb + lq) * 20 + kb + lr]);
                b[nt][1] = f2tf(Wb[(nb + lq) * 20 + kb + 4 + lr]);
            }
#pragma unroll
            for (int mt = 0; mt < 2; mt++)
#pragma unroll
                for (int nt = 0; nt < 4; nt++)
                    mma_tf32(acc[mt][nt], a[mt][0], a[mt][1], a[mt][2], a[mt][3],
                             b[nt][0], b[nt][1]);
        }
        __syncthreads();
    }
#pragma unroll
    for (int mt = 0; mt < 2; mt++) {
#pragma unroll
        for (int nt = 0; nt < 4; nt++) {
            int gc = n0 + wn + nt * 8 + 2 * lr;
            float bi0 = bias ? bias[gc] : 0.f;
            float bi1 = bias ? bias[gc + 1] : 0.f;
#pragma unroll
            for (int half = 0; half < 2; half++) {
                int gr = m0 + wm + mt * 16 + lq + half * 8;
                float2 v;
                v.x = alpha * acc[mt][nt][half * 2] + bi0;
                v.y = alpha * acc[mt][nt][half * 2 + 1] + bi1;
                *reinterpret_cast<float2*>(&Cc[(size_t)gr * ldc + gc]) = v;
            }
        }
    }
}

// ---------------- row softmax in-place on [B*N, N] ----------------
__global__ void k_row_softmax(float* __restrict__ E) {
    size_t off = (size_t)blockIdx.x * NNODE;
    __shared__ float row[NNODE];
    __shared__ float sh[8];
    int tid = threadIdx.x;
    float lmax = -3.4e38f;
    for (int i = tid; i < NNODE; i += 256) {
        float v = E[off + i];
        row[i] = v;
        lmax = fmaxf(lmax, v);
    }
    float mx = blockMax(lmax, sh);
    float ls = 0.f;
    for (int i = tid; i < NNODE; i += 256) {
        float e = __expf(row[i] - mx);
        row[i] = e;
        ls += e;
    }
    float Z = blockSum(ls, sh);
    float invZ = 1.f / Z;
    for (int i = tid; i < NNODE; i += 256) E[off + i] = row[i] * invZ;
}

// ---------------- fused LN1 + graph-mix + LN2 ----------------
__global__ void k_ln_fuse(const float* __restrict__ node, const float* __restrict__ edge,
                          const float* __restrict__ s,
                          const float* __restrict__ g1, const float* __restrict__ b1,
                          const float* __restrict__ g2, const float* __restrict__ b2,
                          float* __restrict__ y) {
    int bn = blockIdx.x;
    int b = bn >> 10, n = bn & 1023;
    __shared__ float row[CC];
    __shared__ float sh[8];
    int tid = threadIdx.x;
    const float* xr = node + (size_t)bn * CC;
    float lsum = 0.f, lsq = 0.f;
    for (int c = tid; c < CC; c += 256) {
        float v = xr[c];
        row[c] = v;
        lsum += v;
        lsq += v * v;
    }
    float sum = blockSum(lsum, sh);
    float sq = blockSum(lsq, sh);
    float mean = sum * (1.f / CC);
    float var = sq * (1.f / CC) - mean * mean;
    float inv = rsqrtf(var + LN_EPS);
    float diag = edge[((size_t)b * NNODE + n) * NNODE + n];
    lsum = 0.f;
    lsq = 0.f;
    for (int c = tid; c < CC; c += 256) {
        float nt = (row[c] - mean) * inv * g1[c] + b1[c];
        float n2 = diag * nt * s[b * CC + c] + nt;
        row[c] = n2;
        lsum += n2;
        lsq += n2 * n2;
    }
    float sum2 = blockSum(lsum, sh);
    float sq2 = blockSum(lsq, sh);
    float mean2 = sum2 * (1.f / CC);
    float var2 = sq2 * (1.f / CC) - mean2 * mean2;
    float inv2 = rsqrtf(var2 + LN_EPS);
    float* yr = y + (size_t)bn * CC;
    for (int c = tid; c < CC; c += 256)
        yr[c] = (row[c] - mean2) * inv2 * g2[c] + b2[c];
}

// ================= fused attention per (16-row tile, head, batch) =================
// grid (N/16, NH, B) = 1024 blocks, 256 thr, 112 KB smem, 2 blocks/SM.
#define FA_SMEM_FLOATS 28672
__global__ void __launch_bounds__(256, 2)
k_fattn2(const float* __restrict__ qkv, const float* __restrict__ edge,
         float* __restrict__ nodeout, float* __restrict__ hbuf,
         const float* __restrict__ exp_w, const float* __restrict__ exp_b,
         const float* __restrict__ red_w) {
    extern __shared__ float sm[];
    float* S = sm;
    float* Qh = sm + 16448;
    float* U = sm + 17408;  // staging union
    int n0 = blockIdx.x * 16;
    int h = blockIdx.y;
    int b = blockIdx.z;
    int tid = threadIdx.x, warp = tid >> 5, lane = tid & 31;
    int lq = lane >> 2, lr = lane & 3;
    const float* qbase = qkv + (size_t)b * NNODE * C3;
    const float* kbase = qbase + CC + h * DH;
    const float* vbase = qbase + 2 * CC + h * DH;
    const float* erow = edge + ((size_t)b * NNODE + n0) * NNODE;

    auto stageK = [&](float* buf, int m0) {
#pragma unroll
        for (int i = 0; i < 3; i++) {
            int idx = tid + i * 256;
            if (idx < 640) {
                int r = idx / 10, sg = idx - r * 10;
                cp16(&buf[r * 44 + sg * 4], kbase + (size_t)(m0 + r) * C3 + sg * 4);
            }
        }
    };
    auto stageV = [&](float* buf, int m0) {
#pragma unroll
        for (int i = 0; i < 5; i++) {
            int idx = tid + i * 256;
            int r = idx / 10, sg = idx - r * 10;
            cp16(&buf[r * 44 + sg * 4], vbase + (size_t)(m0 + r) * C3 + sg * 4);
        }
    };

    for (int i = tid; i < 16 * DH; i += 256) {
        int r = i / DH, d = i - r * DH;
        Qh[d * 24 + r] = f2tf_f(qbase[(size_t)(n0 + r) * C3 + h * DH + d]);
    }
    float ew = exp_w[h], eb = exp_b[h];

    // ---- logits: 16 chunks of 64 cols, double-buffered K staging ----
    stageK(U, 0);
    cpcommit();
    for (int c = 0; c < 16; c++) {
        if (c + 1 < 16) {
            stageK(U + ((c + 1) & 1) * 2816, (c + 1) * 64);
            cpcommit();
            cpwait1();
        } else {
            cpwait0();
        }
        __syncthreads();
        const float* Kb = U + (c & 1) * 2816;
        float acc[4] = {};
        int nb = warp * 8;
#pragma unroll
        for (int ks = 0; ks < 5; ks++) {
            int kb = ks * 8;
            unsigned a0 = __float_as_uint(Qh[(kb + lr) * 24 + lq]);
            unsigned a1 = __float_as_uint(Qh[(kb + lr) * 24 + lq + 8]);
            unsigned a2 = __float_as_uint(Qh[(kb + 4 + lr) * 24 + lq]);
            unsigned a3 = __float_as_uint(Qh[(kb + 4 + lr) * 24 + lq + 8]);
            unsigned b0 = f2tf(Kb[(nb + lq) * 44 + kb + lr]);
            unsigned b1 = f2tf(Kb[(nb + lq) * 44 + kb + 4 + lr]);
            mma_tf32(acc, a0, a1, a2, a3, b0, b1);
        }
        int gc = c * 64 + nb + 2 * lr;
        float2 e0 = *reinterpret_cast<const float2*>(&erow[(size_t)lq * NNODE + gc]);
        float2 e1 =
            *reinterpret_cast<const float2*>(&erow[(size_t)(lq + 8) * NNODE + gc]);
        float2 v0, v1;
        v0.x = acc[0] * ATTN_SCALE + ew * e0.x + eb;
        v0.y = acc[1] * ATTN_SCALE + ew * e0.y + eb;
        v1.x = acc[2] * ATTN_SCALE + ew * e1.x + eb;
        v1.y = acc[3] * ATTN_SCALE + ew * e1.y + eb;
        *reinterpret_cast<float2*>(&S[lq * 1028 + gc]) = v0;
        *reinterpret_cast<float2*>(&S[(lq + 8) * 1028 + gc]) = v1;
        __syncthreads();
    }

    stageV(U, 0);
    cpcommit();

    // ---- softmax + per-head ednew contribution (single exp, logits in regs) ----
    float rw = red_w[h];
    float* edh_base = hbuf + (((size_t)(b * NH + h)) * NNODE + n0) * NNODE;
#pragma unroll
    for (int rr = 0; rr < 2; rr++) {
        int r = warp * 2 + rr;
        float l[32];
        float mx = -3.4e38f;
#pragma unroll
        for (int k = 0; k < 32; k++) {
            l[k] = S[r * 1028 + k * 32 + lane];
            mx = fmaxf(mx, l[k]);
        }
        mx = warpRedMax(mx);
        float sum = 0.f;
#pragma unroll
        for (int k = 0; k < 32; k++) {
            float e = __expf(l[k] - mx);
            S[r * 1028 + k * 32 + lane] = e;
            sum += e;
        }
        sum = warpRedSum(sum);
        float invZ = 1.f / sum;
        float* edh = edh_base + (size_t)r * NNODE;
#pragma unroll
        for (int k = 0; k < 32; k++) {
            float p = S[r * 1028 + k * 32 + lane] * invZ;
            S[r * 1028 + k * 32 + lane] = p;
            edh[k * 32 + lane] = rw * (l[k] + p);
        }
    }

    // ---- AV: 8 chunks of 128, double-buffered V staging; warps 0..4 compute ----
    float av[4] = {0.f, 0.f, 0.f, 0.f};
    for (int c = 0; c < 8; c++) {
        if (c + 1 < 8) {
            stageV(U + ((c + 1) & 1) * 5632, (c + 1) * 128);
            cpcommit();
            cpwait1();
        } else {
            cpwait0();
        }
        __syncthreads();
        const float* Vb = U + (c & 1) * 5632;
        int mv0 = c * 128;
        if (warp < 5) {
#pragma unroll
            for (int ks = 0; ks < 16; ks++) {
                int kb = ks * 8;
                unsigned a0 = f2tf(S[lq * 1028 + mv0 + kb + lr]);
                unsigned a1 = f2tf(S[(lq + 8) * 1028 + mv0 + kb + lr]);
                unsigned a2 = f2tf(S[lq * 1028 + mv0 + kb + 4 + lr]);
                unsigned a3 = f2tf(S[(lq + 8) * 1028 + mv0 + kb + 4 + lr]);
                unsigned b0 = f2tf(Vb[(kb + lr) * 44 + warp * 8 + lq]);
                unsigned b1 = f2tf(Vb[(kb + 4 + lr) * 44 + warp * 8 + lq]);
                mma_tf32(av, a0, a1, a2, a3, b0, b1);
            }
        }
        __syncthreads();
    }
    if (warp < 5) {
        float* nbase = nodeout + ((size_t)b * NNODE + n0) * CC;
        int gc = h * DH + warp * 8 + 2 * lr;
        *reinterpret_cast<float2*>(&nbase[(size_t)lq * CC + gc]) =
            make_float2(av[0], av[1]);
        *reinterpret_cast<float2*>(&nbase[(size_t)(lq + 8) * CC + gc]) =
            make_float2(av[2], av[3]);
    }
}

// ------- per (b,n): en=sum_h hbuf+rb; wsum; edge+=en; node_out+=wsum (float4) -------
__global__ void k_edpost(float* __restrict__ edge, const float* __restrict__ hbuf,
                         float* __restrict__ nodeout, const float* __restrict__ red_b) {
    int bn = blockIdx.x;
    int b = bn >> 10, n = bn & 1023;
    __shared__ float row[NNODE];
    __shared__ float sh[8];
    int tid = threadIdx.x;  // 256: one float4 per thread covers the row
    float rb = red_b[0];
    const float* base = hbuf + ((size_t)b * NH * NNODE + n) * NNODE;
    float4 acc = make_float4(rb, rb, rb, rb);
#pragma unroll
    for (int h = 0; h < NH; h++) {
        float4 v = *reinterpret_cast<const float4*>(
            base + (size_t)h * NNODE * NNODE + tid * 4);
        acc.x += v.x;
        acc.y += v.y;
        acc.z += v.z;
        acc.w += v.w;
    }
    *reinterpret_cast<float4*>(&row[tid * 4]) = acc;
    float lmax = fmaxf(fmaxf(acc.x, acc.y), fmaxf(acc.z, acc.w));
    float mx = blockMax(lmax, sh);
    float ls = 0.f, lS = 0.f;
#pragma unroll
    for (int j = 0; j < 4; j++) {
        float v = (&acc.x)[j];
        float e = __expf(v - mx);
        ls += e;
        lS += e * v;
    }
    float Z = blockSum(ls, sh);
    float Ssum = blockSum(lS, sh);
    float wsum = Ssum / Z;
    float* eg = edge + (size_t)bn * NNODE;
    float4 ev = *reinterpret_cast<const float4*>(&eg[tid * 4]);
    ev.x += acc.x;
    ev.y += acc.y;
    ev.z += acc.z;
    ev.w += acc.w;
    *reinterpret_cast<float4*>(&eg[tid * 4]) = ev;
    float* np = nodeout + (size_t)bn * CC;
    for (int c = tid; c < CC; c += 256) np[c] += wsum;
}

// ---------------- launch ----------------
extern "C" void kernel_launch(void* const* d_in, const int* in_sizes, int n_in,
                              void* d_out, int out_size) {
    const float* x = (const float*)d_in[0];
    const float* da_prior = (const float*)d_in[1];
    const float* qk_w = (const float*)d_in[2];
    const float* fcp_w = (const float*)d_in[3];
    const float* fcp_b = (const float*)d_in[4];
    const float* ln1_g = (const float*)d_in[5];
    const float* ln1_b = (const float*)d_in[6];
    const float* gln_g = (const float*)d_in[7];
    const float* gln_b = (const float*)d_in[8];
    const float* qkv_w = (const float*)d_in[9];
    const float* qkv_b = (const float*)d_in[10];
    const float* proj_w = (const float*)d_in[11];
    const float* proj_b = (const float*)d_in[12];
    const float* exp_w = (const float*)d_in[13];
    const float* exp_b = (const float*)d_in[14];
    const float* red_w = (const float*)d_in[15];
    const float* red_b = (const float*)d_in[16];
    float* out = (float*)d_out;

    float *p_node, *p_qk, *p_y, *p_qkv, *p_edge, *p_hbuf, *p_nodeout, *p_s;
    cudaGetSymbolAddress((void**)&p_node, g_node);
    cudaGetSymbolAddress((void**)&p_qk, g_qk);
    cudaGetSymbolAddress((void**)&p_y, g_y);
    cudaGetSymbolAddress((void**)&p_qkv, g_qkv);
    cudaGetSymbolAddress((void**)&p_edge, g_edge);
    cudaGetSymbolAddress((void**)&p_hbuf, g_hbuf);
    cudaGetSymbolAddress((void**)&p_nodeout, g_nodeout);
    cudaGetSymbolAddress((void**)&p_s, g_s);

    static const size_t fa_smem = FA_SMEM_FLOATS * sizeof(float);
    cudaFuncSetAttribute(k_fattn2, cudaFuncAttributeMaxDynamicSharedMemorySize,
                         (int)fa_smem);

    k_tin<<<dim3(NNODE / 32, CC / 32, BB), dim3(32, 8)>>>(x, p_node);
    k_prior<<<3, 256>>>(da_prior, fcp_w, fcp_b, p_s);
    // qk : M=2048, N=640, K=320
    k_mm<<<dim3(C2 / 64, (BB * NNODE) / 64, 1), 128>>>(
        p_node, CC, 0, qk_w, CC, 0, p_qk, C2, 0, CC, 1.f, nullptr);
    // edge logits per batch
    k_mm<<<dim3(NNODE / 64, NNODE / 64, BB), 128>>>(
        p_qk, C2, (size_t)NNODE * C2, p_qk + CC, C2, (size_t)NNODE * C2,
        p_edge, NNODE, (size_t)NNODE * NNODE, CC, EDGE_SCALE, nullptr);
    k_row_softmax<<<BB * NNODE, 256>>>(p_edge);

    for (int l = 0; l < LLAYERS; l++) {
        k_ln_fuse<<<BB * NNODE, 256>>>(p_node, p_edge, p_s,
                                       ln1_g + l * CC, ln1_b + l * CC,
                                       gln_g + l * CC, gln_b + l * CC, p_y);
        k_mm<<<dim3(C3 / 64, (BB * NNODE) / 64, 1), 128>>>(
            p_y, CC, 0, qkv_w + (size_t)l * C3 * CC, CC, 0,
            p_qkv, C3, 0, CC, 1.f, qkv_b + l * C3);
        k_fattn2<<<dim3(NNODE / 16, NH, BB), 256, fa_smem>>>(
            p_qkv, p_edge, p_nodeout, p_hbuf, exp_w + l * NH, exp_b + l * NH,
            red_w + l * NH);
        k_edpost<<<BB * NNODE, 256>>>(p_edge, p_hbuf, p_nodeout, red_b + l);
        k_mm<<<dim3(CC / 64, (BB * NNODE) / 64, 1), 128>>>(
            p_nodeout, CC, 0, proj_w + (size_t)l * CC * CC, CC, 0,
            p_node, CC, 0, CC, 1.f, proj_b + l * CC);
    }

    k_tout<<<dim3(NNODE / 32, CC / 32, BB), dim3(32, 8)>>>(p_node, out);
}